// round 1
// baseline (speedup 1.0000x reference)
#include <cuda_runtime.h>

#define BB 64
#define CC 768
#define HW 24
#define HID 768

// ---------------- device scratch (no allocations allowed) ----------------
__device__ float g_wx[BB][16];
__device__ float g_wy[BB][16];
__device__ int   g_wlo[BB], g_wlen[BB], g_hlo[BB], g_hlen[BB];
__device__ float g_feat[BB * CC];
__device__ float g_pa[3][BB * HID];   // layer1 K-split partials
__device__ float g_pb[3][BB * HID];   // layer2 K-split partials

// ---------------- hat CDF ----------------
__device__ __forceinline__ float hat_cdf(float t) {
    if (t <= -1.f) return 0.f;
    if (t <= 0.f) { float u = t + 1.f; return 0.5f * u * u; }
    if (t <= 1.f) { float u = 1.f - t; return 1.f - 0.5f * u * u; }
    return 1.f;
}

// ---------------- kernel 1: per-batch box weights (telescoped) ----------------
__global__ void prep_kernel(const float* __restrict__ sb) {
    int b = threadIdx.x;
    if (b >= BB) return;
    float x0 = sb[b * 4 + 0] * (float)HW;
    float y0 = sb[b * 4 + 1] * (float)HW;
    float x1 = sb[b * 4 + 2] * (float)HW;
    float y1 = sb[b * 4 + 3] * (float)HW;
    float scale = 1.f / ((x1 - x0) * (y1 - y0));   // = 1/(16*bw*bh), always > 0 here

    int wlo = max(0, (int)floorf(x0 - 1.f) + 1);
    int whi = min(HW - 1, (int)ceilf(x1 + 1.f) - 1);
    int hlo = max(0, (int)floorf(y0 - 1.f) + 1);
    int hhi = min(HW - 1, (int)ceilf(y1 + 1.f) - 1);
    g_wlo[b] = wlo; g_wlen[b] = whi - wlo + 1;
    g_hlo[b] = hlo; g_hlen[b] = hhi - hlo + 1;

    for (int i = 0; i <= whi - wlo; i++) {
        float c = (float)(wlo + i);
        g_wx[b][i] = hat_cdf(x1 - c) - hat_cdf(x0 - c);
    }
    for (int i = 0; i <= hhi - hlo; i++) {
        float c = (float)(hlo + i);
        g_wy[b][i] = (hat_cdf(y1 - c) - hat_cdf(y0 - c)) * scale;
    }
}

// ---------------- kernel 2: sparse weighted pooling -> feat[64,768] ----------------
// grid (8, 64): blockIdx.y = batch, blockIdx.x = 96-channel chunk. 8 warps x 12 ch.
__global__ __launch_bounds__(256) void pool_kernel(const float* __restrict__ X) {
    __shared__ float s_wprod[256];
    __shared__ int   s_off[256];

    const int b = blockIdx.y;
    const int t = threadIdx.x;
    const int wlen = g_wlen[b], hlen = g_hlen[b];
    const int wlo  = g_wlo[b],  hlo  = g_hlo[b];
    const int n = wlen * hlen;                     // <= 225

    for (int i = t; i < n; i += 256) {
        int h = i / wlen;
        int w = i - h * wlen;
        s_wprod[i] = g_wy[b][h] * g_wx[b][w];
        s_off[i]   = (hlo + h) * HW + (wlo + w);
    }
    __syncthreads();

    const int wid = t >> 5, lane = t & 31;
    const int cbase = blockIdx.x * 96 + wid * 12;
    for (int j = 0; j < 12; j++) {
        int c = cbase + j;
        const float* xp = X + (size_t)(b * CC + c) * (HW * HW);
        float acc = 0.f;
        for (int i = lane; i < n; i += 32)
            acc = fmaf(s_wprod[i], __ldg(xp + s_off[i]), acc);
        #pragma unroll
        for (int s = 16; s; s >>= 1) acc += __shfl_xor_sync(0xffffffffu, acc, s);
        if (lane == 0) g_feat[b * CC + c] = acc;
    }
}

// ---------------- GEMM body: C_part[64,768] tile, K-split=3 ----------------
// grid (6, 8, 3); block 256 = 8 warps. Warp = 1 row, lane = 4 cols (float4).
// FUSE: A = relu(P0 + P1 + P2 + bias_in)  (combines previous layer's partials)
template <bool FUSE>
__device__ __forceinline__ void gemm_body(
    const float* __restrict__ P0, const float* __restrict__ P1,
    const float* __restrict__ P2, const float* __restrict__ bias_in,
    const float* __restrict__ W,  float* __restrict__ outp)
{
    __shared__ float As[8][256];
    const int c0 = blockIdx.x * 128;
    const int r0 = blockIdx.y * 8;
    const int k0 = blockIdx.z * 256;
    const int t = threadIdx.x;

    // Load A tile: 8 rows x 256 k = 512 float4, 2 per thread
    for (int q = t; q < 512; q += 256) {
        int r  = q >> 6;
        int kk = (q & 63) << 2;
        int idx = (r0 + r) * HID + k0 + kk;
        float4 v = *(const float4*)(P0 + idx);
        if (FUSE) {
            float4 v1 = *(const float4*)(P1 + idx);
            float4 v2 = *(const float4*)(P2 + idx);
            float4 bb = *(const float4*)(bias_in + k0 + kk);
            v.x = fmaxf(v.x + v1.x + v2.x + bb.x, 0.f);
            v.y = fmaxf(v.y + v1.y + v2.y + bb.y, 0.f);
            v.z = fmaxf(v.z + v1.z + v2.z + bb.z, 0.f);
            v.w = fmaxf(v.w + v1.w + v2.w + bb.w, 0.f);
        }
        *(float4*)&As[r][kk] = v;
    }
    __syncthreads();

    const int wid = t >> 5, lane = t & 31;
    const float* wp = W + (size_t)k0 * HID + c0 + (lane << 2);
    float4 acc = make_float4(0.f, 0.f, 0.f, 0.f);
    float4 wb0[8], wb1[8];

    #pragma unroll
    for (int j = 0; j < 8; j++) wb0[j] = *(const float4*)(wp + j * HID);
    wp += 8 * HID;

    #pragma unroll 1
    for (int ch = 0; ch < 32; ch += 2) {
        #pragma unroll
        for (int j = 0; j < 8; j++) wb1[j] = *(const float4*)(wp + j * HID);
        wp += 8 * HID;
        #pragma unroll
        for (int j = 0; j < 8; j++) {
            float a = As[wid][ch * 8 + j];
            acc.x = fmaf(a, wb0[j].x, acc.x);
            acc.y = fmaf(a, wb0[j].y, acc.y);
            acc.z = fmaf(a, wb0[j].z, acc.z);
            acc.w = fmaf(a, wb0[j].w, acc.w);
        }
        if (ch + 2 < 32) {
            #pragma unroll
            for (int j = 0; j < 8; j++) wb0[j] = *(const float4*)(wp + j * HID);
            wp += 8 * HID;
        }
        #pragma unroll
        for (int j = 0; j < 8; j++) {
            float a = As[wid][ch * 8 + 8 + j];
            acc.x = fmaf(a, wb1[j].x, acc.x);
            acc.y = fmaf(a, wb1[j].y, acc.y);
            acc.z = fmaf(a, wb1[j].z, acc.z);
            acc.w = fmaf(a, wb1[j].w, acc.w);
        }
    }

    *(float4*)(outp + (size_t)blockIdx.z * (BB * HID)
               + (r0 + wid) * HID + c0 + (lane << 2)) = acc;
}

__global__ __launch_bounds__(256) void gemm1_kernel(const float* __restrict__ W) {
    gemm_body<false>(g_feat, nullptr, nullptr, nullptr, W, &g_pa[0][0]);
}

__global__ __launch_bounds__(256) void gemm2_kernel(const float* __restrict__ b1,
                                                    const float* __restrict__ W) {
    gemm_body<true>(&g_pa[0][0], &g_pa[1][0], &g_pa[2][0], b1, W, &g_pb[0][0]);
}

// ---------------- kernel 5: final 768 -> 1 with fused partial-combine+bias+relu ----
__global__ __launch_bounds__(256) void final_kernel(
    const float* __restrict__ b2, const float* __restrict__ w3,
    const float* __restrict__ b3, float* __restrict__ out)
{
    __shared__ float red[8];
    const int b = blockIdx.x, t = threadIdx.x;
    float acc = 0.f;
    for (int k = t; k < HID; k += 256) {
        int idx = b * HID + k;
        float v = g_pb[0][idx] + g_pb[1][idx] + g_pb[2][idx] + b2[k];
        acc = fmaf(fmaxf(v, 0.f), w3[k], acc);
    }
    #pragma unroll
    for (int s = 16; s; s >>= 1) acc += __shfl_xor_sync(0xffffffffu, acc, s);
    if ((t & 31) == 0) red[t >> 5] = acc;
    __syncthreads();
    if (t < 8) {
        acc = red[t];
        #pragma unroll
        for (int s = 4; s; s >>= 1) acc += __shfl_xor_sync(0xffu, acc, s);
        if (t == 0) out[b] = acc + b3[0];
    }
}

// ---------------- launch ----------------
extern "C" void kernel_launch(void* const* d_in, const int* in_sizes, int n_in,
                              void* d_out, int out_size) {
    const float* X  = (const float*)d_in[0];
    const float* sb = (const float*)d_in[1];
    const float* w1 = (const float*)d_in[2];
    const float* b1 = (const float*)d_in[3];
    const float* w2 = (const float*)d_in[4];
    const float* b2 = (const float*)d_in[5];
    const float* w3 = (const float*)d_in[6];
    const float* b3 = (const float*)d_in[7];
    float* out = (float*)d_out;

    prep_kernel<<<1, 64>>>(sb);
    pool_kernel<<<dim3(8, 64), 256>>>(X);
    dim3 g(6, 8, 3);
    gemm1_kernel<<<g, 256>>>(w1);
    gemm2_kernel<<<g, 256>>>(b1, w2);
    final_kernel<<<64, 256>>>(b2, w3, b3, out);
}